// round 2
// baseline (speedup 1.0000x reference)
#include <cuda_runtime.h>
#include <math.h>

// Problem dims
#define B_ 32
#define S_ 2048
#define H_ 512
#define V_ 128
#define P_ 256
#define M_ 128
#define SLOTS_ 64
#define L_ 2
#define IT_ 2816
#define IM_ 768
#define HALT_STEPS_ 4

#define SQRT_H_ 22.62741699796952f
#define INV_SQRT_M_ 0.08838834764831845f

// Output offsets (fp32 elements)
#define LOGITS_OFF 0
#define HALT_OFF   (HALT_STEPS_*B_*S_*V_)            // 33554432
#define ZL_OFF     (HALT_OFF + HALT_STEPS_*B_)       // 33554560
#define HOUT_OFF   (ZL_OFF + B_*S_*H_)               // 67108992
#define MEM_OFF    (HOUT_OFF + B_*P_)                // 67117184

// Scratch state (static device memory; no runtime allocation)
__device__ float g_z[B_*S_*H_];          // current z_L, (B,S,H)
__device__ float g_t[B_*S_*H_];          // transposed,  (B,H,S)
__device__ float g_act[B_*S_*IM_];       // 65536*768 floats >= 16384*2816
__device__ float g_h[B_*P_];
__device__ float g_mem[B_*SLOTS_*M_];
__device__ float g_pooled[B_*H_];
__device__ float g_ctx[B_*H_];
__device__ float g_film[B_*2*H_];

__device__ __forceinline__ float silu_f(float v){ return v/(1.0f+expf(-v)); }

// ---------------------------------------------------------------------------
// copy (vectorized)
__global__ void copy4_kernel(float4* __restrict__ dst, const float4* __restrict__ src, int n4){
    int i = blockIdx.x*blockDim.x + threadIdx.x;
    if (i < n4) dst[i] = src[i];
}

// ---------------------------------------------------------------------------
// pooled[b,h] = mean_s z[b,s,h]
__global__ void pooled_kernel(){
    int b = blockIdx.x, h = threadIdx.x;   // 512 threads
    const float* p = g_z + (size_t)b*S_*H_ + h;
    float acc0=0.f, acc1=0.f, acc2=0.f, acc3=0.f;
    #pragma unroll 4
    for (int s=0; s<S_; s+=4){
        acc0 += p[(s+0)*H_];
        acc1 += p[(s+1)*H_];
        acc2 += p[(s+2)*H_];
        acc3 += p[(s+3)*H_];
    }
    g_pooled[b*H_+h] = (acc0+acc1+acc2+acc3) * (1.0f/S_);
}

// ---------------------------------------------------------------------------
// planner + memory attention + mem update; one block per batch, 256 threads
__global__ void planner_kernel(
    const float* __restrict__ w1, const float* __restrict__ b1,
    const float* __restrict__ w2, const float* __restrict__ b2,
    const float* __restrict__ hdw, const float* __restrict__ hdb,
    const float* __restrict__ filmw, const float* __restrict__ filmb,
    const float* __restrict__ haltw, const float* __restrict__ haltb,
    const float* __restrict__ qw, const float* __restrict__ qb,
    const float* __restrict__ kw, const float* __restrict__ kb,
    const float* __restrict__ vw, const float* __restrict__ vb,
    const float* __restrict__ gw, const float* __restrict__ gb,
    const float* __restrict__ ow, const float* __restrict__ ob,
    float* __restrict__ halt_out)
{
    int b = blockIdx.x, tid = threadIdx.x;
    __shared__ float x[768];
    __shared__ float a1s[256];
    __shared__ float hm[256];
    __shared__ float qv[128], kv2[128], vv[128];
    __shared__ float rq[64], rk[64];
    __shared__ float ctxm[128];
    __shared__ float sgate;

    for (int i=tid; i<512; i+=256) x[i] = g_pooled[b*H_+i];
    x[512+tid] = g_h[b*P_+tid];
    __syncthreads();

    // a1 = gelu(W1 [pooled,h] + b1)  (exact gelu)
    {
        float acc = b1[tid];
        const float* w = w1 + tid*768;
        #pragma unroll 4
        for (int k2=0;k2<768;k2++) acc += w[k2]*x[k2];
        a1s[tid] = 0.5f*acc*(1.0f + erff(acc*0.70710678118654752f));
    }
    __syncthreads();
    // h_mid = W2 a1 + b2
    {
        float acc = b2[tid];
        const float* w = w2 + tid*256;
        #pragma unroll 4
        for (int k2=0;k2<256;k2++) acc += w[k2]*a1s[k2];
        hm[tid] = acc;
    }
    __syncthreads();
    // h += h_delta(h_mid)
    {
        float acc = hdb[tid];
        const float* w = hdw + tid*256;
        #pragma unroll 4
        for (int k2=0;k2<256;k2++) acc += w[k2]*hm[k2];
        g_h[b*P_+tid] = x[512+tid] + acc;
    }
    // film
    for (int j=tid; j<2*H_; j+=256){
        float acc = filmb[j];
        const float* w = filmw + j*256;
        #pragma unroll 4
        for (int k2=0;k2<256;k2++) acc += w[k2]*hm[k2];
        g_film[b*2*H_+j] = acc;
    }
    // halt logit / gate
    if (tid==0){
        float acc = haltb[0];
        for (int k2=0;k2<256;k2++) acc += haltw[k2]*hm[k2];
        halt_out[b] = acc;
    }
    if (tid==1){
        float acc = gb[0];
        for (int k2=0;k2<256;k2++) acc += gw[k2]*hm[k2];
        sgate = 1.0f/(1.0f+expf(-acc));
    }
    // q, k, v
    if (tid<128){
        float aq=qb[tid], ak=kb[tid], av=vb[tid];
        const float* wq=qw+tid*256; const float* wk=kw+tid*256; const float* wv=vw+tid*256;
        #pragma unroll 4
        for (int k2=0;k2<256;k2++){ float hh=hm[k2]; aq+=wq[k2]*hh; ak+=wk[k2]*hh; av+=wv[k2]*hh; }
        qv[tid]=aq; kv2[tid]=ak; vv[tid]=av;
    }
    __syncthreads();

    const float* memb = g_mem + b*SLOTS_*M_;
    if (tid<64){
        float aq=0.f, ak=0.f;
        const float* m = memb + tid*M_;
        #pragma unroll 4
        for (int d2=0; d2<128; d2++){ float mv=m[d2]; aq+=mv*qv[d2]; ak+=mv*kv2[d2]; }
        rq[tid]=aq*INV_SQRT_M_;
        rk[tid]=ak*INV_SQRT_M_;
    }
    __syncthreads();
    if (tid==0){
        float mx=-1e30f; for (int n2=0;n2<64;n2++) mx=fmaxf(mx,rq[n2]);
        float ssum=0.f;  for (int n2=0;n2<64;n2++){ float e=expf(rq[n2]-mx); rq[n2]=e; ssum+=e; }
        float inv=1.0f/ssum; for (int n2=0;n2<64;n2++) rq[n2]*=inv;
    }
    if (tid==1){
        float mx=-1e30f; for (int n2=0;n2<64;n2++) mx=fmaxf(mx,rk[n2]);
        float ssum=0.f;  for (int n2=0;n2<64;n2++){ float e=expf(rk[n2]-mx); rk[n2]=e; ssum+=e; }
        float inv=1.0f/ssum; for (int n2=0;n2<64;n2++) rk[n2]*=inv;
    }
    __syncthreads();
    // ctx_m = r_attn @ mem
    if (tid<128){
        float acc=0.f;
        #pragma unroll 4
        for (int n2=0;n2<64;n2++) acc += rq[n2]*memb[n2*M_+tid];
        ctxm[tid]=acc;
    }
    __syncthreads();
    // ctx = memo(ctx_m)
    for (int j=tid; j<H_; j+=256){
        float acc = ob[j];
        const float* w = ow + j*M_;
        #pragma unroll 4
        for (int d2=0; d2<128; d2++) acc += w[d2]*ctxm[d2];
        g_ctx[b*H_+j]=acc;
    }
    // mem update (reads only its own element + rk/vv/sgate)
    float gv = sgate;
    for (int idx=tid; idx<SLOTS_*M_; idx+=256){
        int n2 = idx>>7, d2 = idx&127;
        float w = rk[n2]*gv;
        g_mem[b*SLOTS_*M_+idx] = memb[idx]*(1.0f-w) + w*vv[d2];
    }
}

// ---------------------------------------------------------------------------
// z += sqrt(H)*embed[token] + ctx
__global__ void z_update_kernel(const int* __restrict__ inputs, const float* __restrict__ embed_w){
    int idx = blockIdx.x*blockDim.x + threadIdx.x;   // B*S*H elements
    int h  = idx & (H_-1);
    int bs = idx >> 9;
    int b  = bs >> 11;
    int tok = inputs[bs];
    g_z[idx] += SQRT_H_*embed_w[tok*H_+h] + g_ctx[b*H_+h];
}

// ---------------------------------------------------------------------------
// transpose (B,S,H) -> (B,H,S)
__global__ void transpose_zt(){
    __shared__ float tile[32][33];
    int b = blockIdx.z;
    int s0 = blockIdx.x*32, h0 = blockIdx.y*32;
    int h = h0 + threadIdx.x;
    for (int r=threadIdx.y; r<32; r+=8)
        tile[r][threadIdx.x] = g_z[(size_t)b*S_*H_ + (size_t)(s0+r)*H_ + h];
    __syncthreads();
    int s = s0 + threadIdx.x;
    for (int r=threadIdx.y; r<32; r+=8)
        g_t[(size_t)b*H_*S_ + (size_t)(h0+r)*S_ + s] = tile[threadIdx.x][r];
}

// transpose back (B,H,S) -> (B,S,H) with FiLM: z = t*(1+scale_h)+shift_h
__global__ void transpose_tz_film(){
    __shared__ float tile[32][33];
    int b = blockIdx.z;
    int s0 = blockIdx.x*32, h0 = blockIdx.y*32;
    int s = s0 + threadIdx.x;
    for (int r=threadIdx.y; r<32; r+=8)
        tile[r][threadIdx.x] = g_t[(size_t)b*H_*S_ + (size_t)(h0+r)*S_ + s];
    __syncthreads();
    int h = h0 + threadIdx.x;
    float sc = 1.0f + g_film[b*2*H_ + h];
    float sh = g_film[b*2*H_ + H_ + h];
    for (int r=threadIdx.y; r<32; r+=8)
        g_z[(size_t)b*S_*H_ + (size_t)(s0+r)*H_ + h] = tile[threadIdx.x][r]*sc + sh;
}

// ---------------------------------------------------------------------------
// in-place rmsnorm of rows of length D
__global__ void rmsnorm_kernel(float* __restrict__ x, int D){
    int row = blockIdx.x;
    float* p = x + (size_t)row*D;
    float acc=0.f;
    for (int i=threadIdx.x; i<D; i+=256){ float v=p[i]; acc += v*v; }
    __shared__ float red[256];
    red[threadIdx.x]=acc; __syncthreads();
    for (int s=128; s>0; s>>=1){
        if (threadIdx.x < s) red[threadIdx.x] += red[threadIdx.x+s];
        __syncthreads();
    }
    float scale = rsqrtf(red[0]/(float)D + 1e-5f);
    for (int i=threadIdx.x; i<D; i+=256) p[i] *= scale;
}

// ---------------------------------------------------------------------------
// SGEMM: C[R,N] = A[R,K] @ B[N,K]^T, tiles 128x64x16, 256 threads, 8x4/thread
// MODE 0: C = acc (plain store)
// MODE 1: C = silu(A@Bg^T) * (A@Bu^T)     (fused SwiGLU)
// MODE 2: C += acc                         (fused residual add)
// Requires: R%128==0, N%64==0, K%16==0 (true for all call sites).
template<int MODE>
__global__ void __launch_bounds__(256) gemm_kernel(
    const float* __restrict__ A, const float* __restrict__ Bg,
    const float* __restrict__ Bu, float* __restrict__ C,
    int K, int N)
{
    __shared__ float As[16][132];
    __shared__ float Bgs[16][68];
    __shared__ float Bus[16][68];
    const int tid = threadIdx.x;
    const int tx = tid & 15, ty = tid >> 4;
    const int rowBase = blockIdx.y*128;
    const int colBase = blockIdx.x*64;

    float accG[8][4];
    float accU[8][4];
    #pragma unroll
    for (int i=0;i<8;i++)
        #pragma unroll
        for (int j=0;j<4;j++){ accG[i][j]=0.f; accU[i][j]=0.f; }

    const int mA = tid>>2, kqA=(tid&3)*4;
    const float* Aptr  = A + (rowBase+mA)*K + kqA;
    const float* Aptr2 = A + (rowBase+mA+64)*K + kqA;
    const float* Bgptr = Bg + (colBase+mA)*K + kqA;
    const float* Buptr = (MODE==1) ? (Bu + (colBase+mA)*K + kqA) : Bg;

    for (int k0=0; k0<K; k0+=16){
        float4 va  = *(const float4*)(Aptr  + k0);
        float4 va2 = *(const float4*)(Aptr2 + k0);
        float4 vb  = *(const float4*)(Bgptr + k0);
        float4 vu = make_float4(0.f,0.f,0.f,0.f);
        if (MODE==1) vu = *(const float4*)(Buptr + k0);

        As[kqA+0][mA]=va.x;  As[kqA+1][mA]=va.y;  As[kqA+2][mA]=va.z;  As[kqA+3][mA]=va.w;
        As[kqA+0][mA+64]=va2.x; As[kqA+1][mA+64]=va2.y; As[kqA+2][mA+64]=va2.z; As[kqA+3][mA+64]=va2.w;
        Bgs[kqA+0][mA]=vb.x; Bgs[kqA+1][mA]=vb.y; Bgs[kqA+2][mA]=vb.z; Bgs[kqA+3][mA]=vb.w;
        if (MODE==1){
            Bus[kqA+0][mA]=vu.x; Bus[kqA+1][mA]=vu.y; Bus[kqA+2][mA]=vu.z; Bus[kqA+3][mA]=vu.w;
        }
        __syncthreads();

        #pragma unroll
        for (int k=0;k<16;k++){
            float a[8];
            float4 t0 = *(const float4*)&As[k][ty*8];
            float4 t1 = *(const float4*)&As[k][ty*8+4];
            a[0]=t0.x;a[1]=t0.y;a[2]=t0.z;a[3]=t0.w;a[4]=t1.x;a[5]=t1.y;a[6]=t1.z;a[7]=t1.w;
            float4 bgv = *(const float4*)&Bgs[k][tx*4];
            float bgl[4]={bgv.x,bgv.y,bgv.z,bgv.w};
            float bul[4]={0.f,0.f,0.f,0.f};
            if (MODE==1){
                float4 buv = *(const float4*)&Bus[k][tx*4];
                bul[0]=buv.x;bul[1]=buv.y;bul[2]=buv.z;bul[3]=buv.w;
            }
            #pragma unroll
            for (int i=0;i<8;i++){
                #pragma unroll
                for (int j=0;j<4;j++){
                    accG[i][j] += a[i]*bgl[j];
                    if (MODE==1) accU[i][j] += a[i]*bul[j];
                }
            }
        }
        __syncthreads();
    }

    #pragma unroll
    for (int i=0;i<8;i++){
        int r = rowBase + ty*8 + i;
        float* cp = C + (size_t)r*N + colBase + tx*4;
        float4 o;
        if (MODE==0){
            o.x=accG[i][0]; o.y=accG[i][1]; o.z=accG[i][2]; o.w=accG[i][3];
        } else if (MODE==1){
            o.x=silu_f(accG[i][0])*accU[i][0];
            o.y=silu_f(accG[i][1])*accU[i][1];
            o.z=silu_f(accG[i][2])*accU[i][2];
            o.w=silu_f(accG[i][3])*accU[i][3];
        } else {
            float4 c = *(const float4*)cp;
            o.x=c.x+accG[i][0]; o.y=c.y+accG[i][1]; o.z=c.z+accG[i][2]; o.w=c.w+accG[i][3];
        }
        *(float4*)cp = o;
    }
}

// ---------------------------------------------------------------------------
extern "C" void kernel_launch(void* const* d_in, const int* in_sizes, int n_in,
                              void* d_out, int out_size)
{
    const int*   inputs    = (const int*)  d_in[0];
    const float* z_in      = (const float*)d_in[1];
    const float* h_in      = (const float*)d_in[2];
    const float* mem_in    = (const float*)d_in[3];
    const float* embed_w   = (const float*)d_in[4];
    const float* lm_head_w = (const float*)d_in[5];
    const float* w1        = (const float*)d_in[6];
    const float* b1        = (const float*)d_in[7];
    const float* w2        = (const float*)d_in[8];
    const float* b2        = (const float*)d_in[9];
    const float* hdw       = (const float*)d_in[10];
    const float* hdb       = (const float*)d_in[11];
    const float* filmw     = (const float*)d_in[12];
    const float* filmb     = (const float*)d_in[13];
    const float* haltw     = (const float*)d_in[14];
    const float* haltb     = (const float*)d_in[15];
    const float* qw        = (const float*)d_in[16];
    const float* qb        = (const float*)d_in[17];
    const float* kw        = (const float*)d_in[18];
    const float* kb        = (const float*)d_in[19];
    const float* vw        = (const float*)d_in[20];
    const float* vb        = (const float*)d_in[21];
    const float* gw        = (const float*)d_in[22];
    const float* gb        = (const float*)d_in[23];
    const float* ow        = (const float*)d_in[24];
    const float* ob        = (const float*)d_in[25];
    const float* wt_gu     = (const float*)d_in[26];
    const float* wt_d      = (const float*)d_in[27];
    const float* wm_gu     = (const float*)d_in[28];
    const float* wm_d      = (const float*)d_in[29];
    float* out = (float*)d_out;

    float *zp, *tp, *actp, *hp, *memp;
    cudaGetSymbolAddress((void**)&zp,   g_z);
    cudaGetSymbolAddress((void**)&tp,   g_t);
    cudaGetSymbolAddress((void**)&actp, g_act);
    cudaGetSymbolAddress((void**)&hp,   g_h);
    cudaGetSymbolAddress((void**)&memp, g_mem);

    // --- state init (each launch: deterministic) ---
    copy4_kernel<<<(B_*S_*H_/4+255)/256, 256>>>((float4*)zp,   (const float4*)z_in,   B_*S_*H_/4);
    copy4_kernel<<<(B_*P_/4+255)/256,    256>>>((float4*)hp,   (const float4*)h_in,   B_*P_/4);
    copy4_kernel<<<(B_*SLOTS_*M_/4+255)/256,256>>>((float4*)memp,(const float4*)mem_in, B_*SLOTS_*M_/4);

    dim3 trBlk(32,8);
    dim3 trGrd(S_/32, H_/32, B_);

    for (int st=0; st<HALT_STEPS_; st++){
        pooled_kernel<<<B_, 512>>>();
        planner_kernel<<<B_, 256>>>(w1,b1,w2,b2,hdw,hdb,filmw,filmb,haltw,haltb,
                                    qw,qb,kw,kb,vw,vb,gw,gb,ow,ob,
                                    out + HALT_OFF + st*B_);
        z_update_kernel<<<B_*S_*H_/256, 256>>>(inputs, embed_w);

        for (int i=0; i<L_; i++){
            // token mixer over S
            transpose_zt<<<trGrd, trBlk>>>();
            gemm_kernel<1><<<dim3(IT_/64, (B_*H_)/128), 256>>>(
                tp, wt_gu + (size_t)i*2*IT_*S_, wt_gu + (size_t)i*2*IT_*S_ + (size_t)IT_*S_,
                actp, S_, IT_);
            gemm_kernel<2><<<dim3(S_/64, (B_*H_)/128), 256>>>(
                actp, wt_d + (size_t)i*S_*IT_, nullptr, tp, IT_, S_);
            rmsnorm_kernel<<<B_*H_, 256>>>(tp, S_);
            transpose_tz_film<<<trGrd, trBlk>>>();
            // channel mixer over H
            gemm_kernel<1><<<dim3(IM_/64, (B_*S_)/128), 256>>>(
                zp, wm_gu + (size_t)i*2*IM_*H_, wm_gu + (size_t)i*2*IM_*H_ + (size_t)IM_*H_,
                actp, H_, IM_);
            gemm_kernel<2><<<dim3(H_/64, (B_*S_)/128), 256>>>(
                actp, wm_d + (size_t)i*H_*IM_, nullptr, zp, IM_, H_);
            rmsnorm_kernel<<<B_*S_, 256>>>(zp, H_);
        }
        // logits for this step
        gemm_kernel<0><<<dim3(V_/64, (B_*S_)/128), 256>>>(
            zp, lm_head_w, nullptr, out + (size_t)st*B_*S_*V_, H_, V_);
    }

    // final state outputs
    copy4_kernel<<<(B_*S_*H_/4+255)/256, 256>>>((float4*)(out + ZL_OFF), (const float4*)zp, B_*S_*H_/4);
    copy4_kernel<<<(B_*P_/4+255)/256,    256>>>((float4*)(out + HOUT_OFF),(const float4*)hp, B_*P_/4);
    copy4_kernel<<<(B_*SLOTS_*M_/4+255)/256,256>>>((float4*)(out + MEM_OFF),(const float4*)memp, B_*SLOTS_*M_/4);
}

// round 4
// speedup vs baseline: 2.2618x; 2.2618x over previous
#include <cuda_runtime.h>
#include <cuda_bf16.h>
#include <math.h>
#include <stdint.h>

// Problem dims
#define B_ 32
#define S_ 2048
#define H_ 512
#define V_ 128
#define P_ 256
#define M_ 128
#define SLOTS_ 64
#define L_ 2
#define IT_ 2816
#define IM_ 768
#define HALT_STEPS_ 4

#define SQRT_H_ 22.62741699796952f
#define INV_SQRT_M_ 0.08838834764831845f

// Output offsets (fp32 elements)
#define HALT_OFF   (HALT_STEPS_*B_*S_*V_)
#define ZL_OFF     (HALT_OFF + HALT_STEPS_*B_)
#define HOUT_OFF   (ZL_OFF + B_*S_*H_)
#define MEM_OFF    (HOUT_OFF + B_*P_)

// ------------------------- static device state -----------------------------
__device__ float g_z[B_*S_*H_];
__device__ float g_t[B_*S_*H_];
__device__ float g_h[B_*P_];
__device__ float g_mem[B_*SLOTS_*M_];
__device__ float g_pp[B_*4*H_];
__device__ float g_pooled[B_*H_];
__device__ float g_ctx[B_*H_];
__device__ float g_film[B_*2*H_];

__device__ __nv_bfloat16 g_th[B_*S_*H_],  g_tl[B_*S_*H_];
__device__ __nv_bfloat16 g_zh[B_*S_*H_],  g_zl[B_*S_*H_];
__device__ __nv_bfloat16 g_acth[B_*S_*IM_], g_actl[B_*S_*IM_];

__device__ __nv_bfloat16 g_wtgu_h[L_*2*IT_*S_], g_wtgu_l[L_*2*IT_*S_];
__device__ __nv_bfloat16 g_wtd_h [L_*S_*IT_],   g_wtd_l [L_*S_*IT_];
__device__ __nv_bfloat16 g_wmgu_h[L_*2*IM_*H_], g_wmgu_l[L_*2*IM_*H_];
__device__ __nv_bfloat16 g_wmd_h [L_*H_*IM_],   g_wmd_l [L_*H_*IM_];
__device__ __nv_bfloat16 g_lmh_h [V_*H_],       g_lmh_l [V_*H_];

// ------------------------- PTX helpers (all legal on compute_103) ----------
__device__ __forceinline__ uint32_t smem_u32(const void* p){
    uint32_t a;
    asm("{ .reg .u64 t; cvta.to.shared.u64 t, %1; cvt.u32.u64 %0, t; }" : "=r"(a) : "l"(p));
    return a;
}
__device__ __forceinline__ void cp16(uint32_t s, const void* g){
    asm volatile("cp.async.cg.shared.global [%0], [%1], 16;" :: "r"(s), "l"(g));
}
__device__ __forceinline__ void cp_commit(){ asm volatile("cp.async.commit_group;" ::: "memory"); }
template<int N> __device__ __forceinline__ void cp_wait(){
    asm volatile("cp.async.wait_group %0;" :: "n"(N) : "memory");
}
__device__ __forceinline__ void ldsm4(uint32_t* r, uint32_t addr){
    asm volatile("ldmatrix.sync.aligned.m8n8.x4.shared.b16 {%0,%1,%2,%3}, [%4];"
        : "=r"(r[0]), "=r"(r[1]), "=r"(r[2]), "=r"(r[3]) : "r"(addr));
}
__device__ __forceinline__ void mma16816(float* c, const uint32_t* a, uint32_t b0, uint32_t b1){
    asm volatile("mma.sync.aligned.m16n8k16.row.col.f32.bf16.bf16.f32 "
        "{%0,%1,%2,%3}, {%4,%5,%6,%7}, {%8,%9}, {%0,%1,%2,%3};"
        : "+f"(c[0]), "+f"(c[1]), "+f"(c[2]), "+f"(c[3])
        : "r"(a[0]), "r"(a[1]), "r"(a[2]), "r"(a[3]), "r"(b0), "r"(b1));
}
__device__ __forceinline__ void split2(float x, __nv_bfloat16& hi, __nv_bfloat16& lo){
    hi = __float2bfloat16(x);
    lo = __float2bfloat16(x - __bfloat162float(hi));
}

// ------------------------- warp-MMA GEMM -----------------------------------
// C[R,N] = A[R,K] @ B[N,K]^T with split-bf16 operands (hi,lo), fp32 accum.
// MODE 0: Cf = result
// MODE 1: Oh/Ol = split(silu(A@Bg^T) * (A@Bu^T))
// MODE 2: Cf += result
// CTA tile 128x128, K-chunk 64 bf16 (128B rows, SW128-style XOR swizzle),
// 8 warps (2x4), warp tile 64x32, mma.sync m16n8k16 bf16, 2-stage cp.async.
template<int MODE>
__global__ void __launch_bounds__(256,1) mma_gemm(
    const __nv_bfloat16* __restrict__ Ah,  const __nv_bfloat16* __restrict__ Al,
    const __nv_bfloat16* __restrict__ Bh,  const __nv_bfloat16* __restrict__ Bl,
    const __nv_bfloat16* __restrict__ Buh, const __nv_bfloat16* __restrict__ Bul,
    float* __restrict__ Cf,
    __nv_bfloat16* __restrict__ Oh, __nv_bfloat16* __restrict__ Ol,
    int K, int N)
{
    constexpr int NT = (MODE==1) ? 6 : 4;
    constexpr int TILE_B = 16384;            // 128 rows x 128 bytes
    constexpr int STAGE  = NT*TILE_B;
    extern __shared__ char dsm[];
    const uint32_t sb = smem_u32(dsm);
    const int tid  = threadIdx.x;
    const int lane = tid & 31, warp = tid >> 5;
    const int wm = warp >> 2, wn = warp & 3;
    const int rowBase = blockIdx.y*128;
    const int colBase = blockIdx.x*128;

    const uint32_t tiles0 = sb;
    const uint32_t tiles1 = sb + STAGE;

    const __nv_bfloat16* ps[6];
    ps[0] = Ah + (size_t)rowBase*K;  ps[1] = Al + (size_t)rowBase*K;
    ps[2] = Bh + (size_t)colBase*K;  ps[3] = Bl + (size_t)colBase*K;
    if (MODE==1){ ps[4] = Buh + (size_t)colBase*K; ps[5] = Bul + (size_t)colBase*K; }
    else        { ps[4] = Ah; ps[5] = Ah; }

    auto load_stage = [&](uint32_t sbase, int k0){
        #pragma unroll
        for (int t = 0; t < NT; t++){
            const __nv_bfloat16* src = ps[t] + k0;
            const uint32_t tb = sbase + (uint32_t)t*TILE_B;
            #pragma unroll
            for (int it = 0; it < 4; it++){
                int i = tid + it*256;
                int row = i >> 3, seg = i & 7;
                uint32_t off = (uint32_t)(row*128 + ((seg ^ (row & 7))<<4));
                cp16(tb + off, (const void*)(src + row*K + seg*8));
            }
        }
    };

    // accumulators: [m-tile][n8-tile][4]
    float G[4][4][4];
    float U[4][4][4];
    #pragma unroll
    for (int a=0;a<4;a++)
        #pragma unroll
        for (int b=0;b<4;b++)
            #pragma unroll
            for (int c=0;c<4;c++){ G[a][b][c]=0.f; if (MODE==1) U[a][b][c]=0.f; }

    const int nCh = K >> 6;
    load_stage(tiles0, 0);  cp_commit();
    load_stage(tiles1, 64); cp_commit();

    // per-thread ldmatrix row components
    const int rA = lane & 15;           // row within 16-row matrix
    const int segSel = lane >> 4;       // 0/1: which 16B within k16
    const int xorA = rA & 7;

    for (int c = 0; c < nCh; c++){
        const uint32_t stg = (c & 1) ? tiles1 : tiles0;
        if (c + 1 < nCh) cp_wait<1>(); else cp_wait<0>();
        __syncthreads();

        const uint32_t aBaseH = stg + (uint32_t)((wm*64 + rA)*128);
        const uint32_t aBaseL = aBaseH + TILE_B;
        const uint32_t bBase  = stg + 2*TILE_B + (uint32_t)((wn*32 + rA)*128);

        #pragma unroll
        for (int ks = 0; ks < 4; ks++){
            const uint32_t segOff = (uint32_t)(((2*ks + segSel) ^ xorA) << 4);
            uint32_t aH[4][4], aL[4][4];
            #pragma unroll
            for (int mt = 0; mt < 4; mt++){
                ldsm4(aH[mt], aBaseH + mt*16*128 + segOff);
                ldsm4(aL[mt], aBaseL + mt*16*128 + segOff);
            }
            #pragma unroll
            for (int bt = 0; bt < 2; bt++){
                uint32_t bh[4], bl[4];
                ldsm4(bh, bBase + bt*16*128 + segOff);                 // Bg hi
                ldsm4(bl, bBase + TILE_B + bt*16*128 + segOff);        // Bg lo
                #pragma unroll
                for (int mt = 0; mt < 4; mt++){
                    mma16816(G[mt][bt*2+0], aH[mt], bh[0], bh[2]);
                    mma16816(G[mt][bt*2+0], aH[mt], bl[0], bl[2]);
                    mma16816(G[mt][bt*2+0], aL[mt], bh[0], bh[2]);
                    mma16816(G[mt][bt*2+1], aH[mt], bh[1], bh[3]);
                    mma16816(G[mt][bt*2+1], aH[mt], bl[1], bl[3]);
                    mma16816(G[mt][bt*2+1], aL[mt], bh[1], bh[3]);
                }
                if (MODE==1){
                    uint32_t uh[4], ul[4];
                    ldsm4(uh, bBase + 2*TILE_B + bt*16*128 + segOff);  // Bu hi
                    ldsm4(ul, bBase + 3*TILE_B + bt*16*128 + segOff);  // Bu lo
                    #pragma unroll
                    for (int mt = 0; mt < 4; mt++){
                        mma16816(U[mt][bt*2+0], aH[mt], uh[0], uh[2]);
                        mma16816(U[mt][bt*2+0], aH[mt], ul[0], ul[2]);
                        mma16816(U[mt][bt*2+0], aL[mt], uh[0], uh[2]);
                        mma16816(U[mt][bt*2+1], aH[mt], uh[1], uh[3]);
                        mma16816(U[mt][bt*2+1], aH[mt], ul[1], ul[3]);
                        mma16816(U[mt][bt*2+1], aL[mt], uh[1], uh[3]);
                    }
                }
            }
        }
        __syncthreads();
        if (c + 2 < nCh){
            load_stage(stg, (c+2)*64);
            cp_commit();
        }
    }

    // ---------------- epilogue ----------------
    const int rEp = rowBase + wm*64 + (lane >> 2);
    const int cEp = colBase + wn*32 + (lane & 3)*2;
    #pragma unroll
    for (int mt = 0; mt < 4; mt++){
        #pragma unroll
        for (int nt = 0; nt < 4; nt++){
            int r0 = rEp + mt*16;
            int cc = cEp + nt*8;
            if (MODE==1){
                #pragma unroll
                for (int half = 0; half < 2; half++){
                    int rr = r0 + half*8;
                    float g0 = G[mt][nt][half*2+0], u0 = U[mt][nt][half*2+0];
                    float g1 = G[mt][nt][half*2+1], u1 = U[mt][nt][half*2+1];
                    float v0 = g0/(1.0f+__expf(-g0))*u0;
                    float v1 = g1/(1.0f+__expf(-g1))*u1;
                    __nv_bfloat16 h0,l0,h1,l1;
                    split2(v0,h0,l0); split2(v1,h1,l1);
                    __nv_bfloat162 hv; hv.x=h0; hv.y=h1;
                    __nv_bfloat162 lv; lv.x=l0; lv.y=l1;
                    size_t off = (size_t)rr*N + cc;
                    *(__nv_bfloat162*)(Oh + off) = hv;
                    *(__nv_bfloat162*)(Ol + off) = lv;
                }
            } else {
                #pragma unroll
                for (int half = 0; half < 2; half++){
                    int rr = r0 + half*8;
                    float2 o;
                    o.x = G[mt][nt][half*2+0];
                    o.y = G[mt][nt][half*2+1];
                    float2* cp2 = (float2*)(Cf + (size_t)rr*N + cc);
                    if (MODE==2){
                        float2 old = *cp2;
                        o.x += old.x; o.y += old.y;
                    }
                    *cp2 = o;
                }
            }
        }
    }
}

// ------------------------- aux kernels -------------------------------------
__global__ void copy4_kernel(float4* __restrict__ dst, const float4* __restrict__ src, int n4){
    int i = blockIdx.x*blockDim.x + threadIdx.x;
    if (i < n4) dst[i] = src[i];
}

__global__ void split_kernel(const float* __restrict__ src,
                             __nv_bfloat16* __restrict__ h, __nv_bfloat16* __restrict__ l, int n){
    int i = (blockIdx.x*blockDim.x + threadIdx.x)*4;
    if (i >= n) return;
    float4 v = *(const float4*)(src + i);
    __nv_bfloat16 h0,l0,h1,l1,h2,l2,h3,l3;
    split2(v.x,h0,l0); split2(v.y,h1,l1); split2(v.z,h2,l2); split2(v.w,h3,l3);
    __nv_bfloat162 hh0; hh0.x=h0; hh0.y=h1;
    __nv_bfloat162 hh1; hh1.x=h2; hh1.y=h3;
    __nv_bfloat162 ll0; ll0.x=l0; ll0.y=l1;
    __nv_bfloat162 ll1; ll1.x=l2; ll1.y=l3;
    ((__nv_bfloat162*)(h+i))[0]=hh0; ((__nv_bfloat162*)(h+i))[1]=hh1;
    ((__nv_bfloat162*)(l+i))[0]=ll0; ((__nv_bfloat162*)(l+i))[1]=ll1;
}

__global__ void pooled1_kernel(){
    int b = blockIdx.x, chunk = blockIdx.y, h = threadIdx.x;
    const float* p = g_z + (size_t)b*S_*H_ + (size_t)chunk*(S_/4)*H_ + h;
    float a0=0.f,a1=0.f,a2=0.f,a3=0.f;
    #pragma unroll 4
    for (int s = 0; s < S_/4; s += 4){
        a0 += p[(s+0)*H_]; a1 += p[(s+1)*H_];
        a2 += p[(s+2)*H_]; a3 += p[(s+3)*H_];
    }
    g_pp[(b*4+chunk)*H_ + h] = a0+a1+a2+a3;
}
__global__ void pooled2_kernel(){
    int b = blockIdx.x, h = threadIdx.x;
    float s = g_pp[(b*4+0)*H_+h] + g_pp[(b*4+1)*H_+h] + g_pp[(b*4+2)*H_+h] + g_pp[(b*4+3)*H_+h];
    g_pooled[b*H_+h] = s * (1.0f/S_);
}

__global__ void planner_kernel(
    const float* __restrict__ w1, const float* __restrict__ b1,
    const float* __restrict__ w2, const float* __restrict__ b2,
    const float* __restrict__ hdw, const float* __restrict__ hdb,
    const float* __restrict__ filmw, const float* __restrict__ filmb,
    const float* __restrict__ haltw, const float* __restrict__ haltb,
    const float* __restrict__ qw, const float* __restrict__ qb,
    const float* __restrict__ kw, const float* __restrict__ kb,
    const float* __restrict__ vw, const float* __restrict__ vb,
    const float* __restrict__ gw, const float* __restrict__ gb,
    const float* __restrict__ ow, const float* __restrict__ ob,
    float* __restrict__ halt_out)
{
    int b = blockIdx.x, tid = threadIdx.x;
    __shared__ float x[768];
    __shared__ float a1s[256];
    __shared__ float hm[256];
    __shared__ float qv[128], kv2[128], vv[128];
    __shared__ float rq[64], rk[64];
    __shared__ float ctxm[128];
    __shared__ float sgate;

    for (int i=tid; i<512; i+=256) x[i] = g_pooled[b*H_+i];
    x[512+tid] = g_h[b*P_+tid];
    __syncthreads();

    {
        float acc = b1[tid];
        const float* w = w1 + tid*768;
        #pragma unroll 4
        for (int k2=0;k2<768;k2++) acc += w[k2]*x[k2];
        a1s[tid] = 0.5f*acc*(1.0f + erff(acc*0.70710678118654752f));
    }
    __syncthreads();
    {
        float acc = b2[tid];
        const float* w = w2 + tid*256;
        #pragma unroll 4
        for (int k2=0;k2<256;k2++) acc += w[k2]*a1s[k2];
        hm[tid] = acc;
    }
    __syncthreads();
    {
        float acc = hdb[tid];
        const float* w = hdw + tid*256;
        #pragma unroll 4
        for (int k2=0;k2<256;k2++) acc += w[k2]*hm[k2];
        g_h[b*P_+tid] = x[512+tid] + acc;
    }
    for (int j=tid; j<2*H_; j+=256){
        float acc = filmb[j];
        const float* w = filmw + j*256;
        #pragma unroll 4
        for (int k2=0;k2<256;k2++) acc += w[k2]*hm[k2];
        g_film[b*2*H_+j] = acc;
    }
    if (tid==0){
        float acc = haltb[0];
        for (int k2=0;k2<256;k2++) acc += haltw[k2]*hm[k2];
        halt_out[b] = acc;
    }
    if (tid==1){
        float acc = gb[0];
        for (int k2=0;k2<256;k2++) acc += gw[k2]*hm[k2];
        sgate = 1.0f/(1.0f+expf(-acc));
    }
    if (tid<128){
        float aq=qb[tid], ak=kb[tid], av=vb[tid];
        const float* wq=qw+tid*256; const float* wk=kw+tid*256; const float* wv=vw+tid*256;
        #pragma unroll 4
        for (int k2=0;k2<256;k2++){ float hh=hm[k2]; aq+=wq[k2]*hh; ak+=wk[k2]*hh; av+=wv[k2]*hh; }
        qv[tid]=aq; kv2[tid]=ak; vv[tid]=av;
    }
    __syncthreads();

    const float* memb = g_mem + b*SLOTS_*M_;
    if (tid<64){
        float aq=0.f, ak=0.f;
        const float* m = memb + tid*M_;
        #pragma unroll 4
        for (int d2=0; d2<128; d2++){ float mv=m[d2]; aq+=mv*qv[d2]; ak+=mv*kv2[d2]; }
        rq[tid]=aq*INV_SQRT_M_;
        rk[tid]=ak*INV_SQRT_M_;
    }
    __syncthreads();
    if (tid==0){
        float mx=-1e30f; for (int n2=0;n2<64;n2++) mx=fmaxf(mx,rq[n2]);
        float ssum=0.f;  for (int n2=0;n2<64;n2++){ float e=expf(rq[n2]-mx); rq[n2]=e; ssum+=e; }
        float inv=1.0f/ssum; for (int n2=0;n2<64;n2++) rq[n2]*=inv;
    }
    if (tid==1){
        float mx=-1e30f; for (int n2=0;n2<64;n2++) mx=fmaxf(mx,rk[n2]);
        float ssum=0.f;  for (int n2=0;n2<64;n2++){ float e=expf(rk[n2]-mx); rk[n2]=e; ssum+=e; }
        float inv=1.0f/ssum; for (int n2=0;n2<64;n2++) rk[n2]*=inv;
    }
    __syncthreads();
    if (tid<128){
        float acc=0.f;
        #pragma unroll 4
        for (int n2=0;n2<64;n2++) acc += rq[n2]*memb[n2*M_+tid];
        ctxm[tid]=acc;
    }
    __syncthreads();
    for (int j=tid; j<H_; j+=256){
        float acc = ob[j];
        const float* w = ow + j*M_;
        #pragma unroll 4
        for (int d2=0; d2<128; d2++) acc += w[d2]*ctxm[d2];
        g_ctx[b*H_+j]=acc;
    }
    float gv = sgate;
    for (int idx=tid; idx<SLOTS_*M_; idx+=256){
        int n2 = idx>>7, d2 = idx&127;
        float w = rk[n2]*gv;
        g_mem[b*SLOTS_*M_+idx] = memb[idx]*(1.0f-w) + w*vv[d2];
    }
}

__global__ void z_update_kernel(const int* __restrict__ inputs, const float* __restrict__ embed_w){
    int idx = blockIdx.x*blockDim.x + threadIdx.x;
    int h  = idx & (H_-1);
    int bs = idx >> 9;
    int b  = bs >> 11;
    int tok = inputs[bs];
    g_z[idx] += SQRT_H_*embed_w[tok*H_+h] + g_ctx[b*H_+h];
}

// (B,S,H) -> (B,H,S), also write bf16 hi/lo splits of t
__global__ void transpose_zt_split(){
    __shared__ float tile[32][33];
    int b = blockIdx.z;
    int s0 = blockIdx.x*32, h0 = blockIdx.y*32;
    int h = h0 + threadIdx.x;
    for (int r=threadIdx.y; r<32; r+=8)
        tile[r][threadIdx.x] = g_z[(size_t)b*S_*H_ + (size_t)(s0+r)*H_ + h];
    __syncthreads();
    int s = s0 + threadIdx.x;
    for (int r=threadIdx.y; r<32; r+=8){
        float v = tile[threadIdx.x][r];
        size_t idx = (size_t)b*H_*S_ + (size_t)(h0+r)*S_ + s;
        g_t[idx] = v;
        __nv_bfloat16 hi, lo; split2(v, hi, lo);
        g_th[idx] = hi; g_tl[idx] = lo;
    }
}

// (B,H,S) -> (B,S,H) with FiLM; also write bf16 hi/lo splits of z
__global__ void transpose_tz_film_split(){
    __shared__ float tile[32][33];
    int b = blockIdx.z;
    int s0 = blockIdx.x*32, h0 = blockIdx.y*32;
    int s = s0 + threadIdx.x;
    for (int r=threadIdx.y; r<32; r+=8)
        tile[r][threadIdx.x] = g_t[(size_t)b*H_*S_ + (size_t)(h0+r)*S_ + s];
    __syncthreads();
    int h = h0 + threadIdx.x;
    float sc = 1.0f + g_film[b*2*H_ + h];
    float sh = g_film[b*2*H_ + H_ + h];
    for (int r=threadIdx.y; r<32; r+=8){
        float v = tile[threadIdx.x][r]*sc + sh;
        size_t idx = (size_t)b*S_*H_ + (size_t)(s0+r)*H_ + h;
        g_z[idx] = v;
        __nv_bfloat16 hi, lo; split2(v, hi, lo);
        g_zh[idx] = hi; g_zl[idx] = lo;
    }
}

__global__ void rmsnorm_t_kernel(){
    int row = blockIdx.x;
    float* p = g_t + (size_t)row*S_;
    float acc=0.f;
    for (int i=threadIdx.x; i<S_; i+=256){ float v=p[i]; acc += v*v; }
    __shared__ float red[256];
    red[threadIdx.x]=acc; __syncthreads();
    for (int s=128; s>0; s>>=1){
        if (threadIdx.x < s) red[threadIdx.x] += red[threadIdx.x+s];
        __syncthreads();
    }
    float scale = rsqrtf(red[0]/(float)S_ + 1e-5f);
    for (int i=threadIdx.x; i<S_; i+=256) p[i] *= scale;
}

__global__ void rmsnorm_z_split_kernel(){
    int row = blockIdx.x;
    float* p = g_z + (size_t)row*H_;
    float acc=0.f;
    for (int i=threadIdx.x; i<H_; i+=256){ float v=p[i]; acc += v*v; }
    __shared__ float red[256];
    red[threadIdx.x]=acc; __syncthreads();
    for (int s=128; s>0; s>>=1){
        if (threadIdx.x < s) red[threadIdx.x] += red[threadIdx.x+s];
        __syncthreads();
    }
    float scale = rsqrtf(red[0]/(float)H_ + 1e-5f);
    for (int i=threadIdx.x; i<H_; i+=256){
        float v = p[i]*scale;
        p[i] = v;
        __nv_bfloat16 hi, lo; split2(v, hi, lo);
        size_t idx = (size_t)row*H_ + i;
        g_zh[idx] = hi; g_zl[idx] = lo;
    }
}

// ---------------------------------------------------------------------------
extern "C" void kernel_launch(void* const* d_in, const int* in_sizes, int n_in,
                              void* d_out, int out_size)
{
    const int*   inputs    = (const int*)  d_in[0];
    const float* z_in      = (const float*)d_in[1];
    const float* h_in      = (const float*)d_in[2];
    const float* mem_in    = (const float*)d_in[3];
    const float* embed_w   = (const float*)d_in[4];
    const float* lm_head_w = (const float*)d_in[5];
    const float* w1        = (const float*)d_in[6];
    const float* b1        = (const float*)d_in[7];
    const float* w2        = (const float*)d_in[8];
    const float* b2        = (const float*)d_in[9];
    const float* hdw       = (const float*)d_in[10];
    const float* hdb       = (const float*)d_in[11];
    const float* filmw     = (const float*)d_in[12];
    const float* filmb     = (const float*)d_in[13];
    const float* haltw     = (const float*)d_in[14];
    const float* haltb     = (const float*)d_in[15];
    const float* qw        = (const float*)d_in[16];
    const float* qb        = (const float*)d_in[17];
    const float* kw        = (const float*)d_in[18];
    const float* kb        = (const float*)d_in[19];
    const float* vw        = (const float*)d_in[20];
    const float* vb        = (const float*)d_in[21];
    const float* gw        = (const float*)d_in[22];
    const float* gb        = (const float*)d_in[23];
    const float* ow        = (const float*)d_in[24];
    const float* ob        = (const float*)d_in[25];
    const float* wt_gu     = (const float*)d_in[26];
    const float* wt_d      = (const float*)d_in[27];
    const float* wm_gu     = (const float*)d_in[28];
    const float* wm_d      = (const float*)d_in[29];
    float* out = (float*)d_out;

    float *zp, *tp, *hp, *memp;
    cudaGetSymbolAddress((void**)&zp,   g_z);
    cudaGetSymbolAddress((void**)&tp,   g_t);
    cudaGetSymbolAddress((void**)&hp,   g_h);
    cudaGetSymbolAddress((void**)&memp, g_mem);

    __nv_bfloat16 *th, *tl, *zh, *zl, *ah, *al;
    __nv_bfloat16 *wtguh, *wtgul, *wtdh, *wtdl, *wmguh, *wmgul, *wmdh, *wmdl, *lmhh, *lmhl;
    cudaGetSymbolAddress((void**)&th, g_th);   cudaGetSymbolAddress((void**)&tl, g_tl);
    cudaGetSymbolAddress((void**)&zh, g_zh);   cudaGetSymbolAddress((void**)&zl, g_zl);
    cudaGetSymbolAddress((void**)&ah, g_acth); cudaGetSymbolAddress((void**)&al, g_actl);
    cudaGetSymbolAddress((void**)&wtguh, g_wtgu_h); cudaGetSymbolAddress((void**)&wtgul, g_wtgu_l);
    cudaGetSymbolAddress((void**)&wtdh,  g_wtd_h);  cudaGetSymbolAddress((void**)&wtdl,  g_wtd_l);
    cudaGetSymbolAddress((void**)&wmguh, g_wmgu_h); cudaGetSymbolAddress((void**)&wmgul, g_wmgu_l);
    cudaGetSymbolAddress((void**)&wmdh,  g_wmd_h);  cudaGetSymbolAddress((void**)&wmdl,  g_wmd_l);
    cudaGetSymbolAddress((void**)&lmhh,  g_lmh_h);  cudaGetSymbolAddress((void**)&lmhl,  g_lmh_l);

    const int SMEM_G  = 2*4*16384;   // MODE 0/2: 128KB
    const int SMEM_G1 = 2*6*16384;   // MODE 1:   192KB
    cudaFuncSetAttribute(mma_gemm<0>, cudaFuncAttributeMaxDynamicSharedMemorySize, SMEM_G);
    cudaFuncSetAttribute(mma_gemm<1>, cudaFuncAttributeMaxDynamicSharedMemorySize, SMEM_G1);
    cudaFuncSetAttribute(mma_gemm<2>, cudaFuncAttributeMaxDynamicSharedMemorySize, SMEM_G);

    // state init
    copy4_kernel<<<(B_*S_*H_/4+255)/256, 256>>>((float4*)zp,   (const float4*)z_in,   B_*S_*H_/4);
    copy4_kernel<<<(B_*P_/4+255)/256,    256>>>((float4*)hp,   (const float4*)h_in,   B_*P_/4);
    copy4_kernel<<<(B_*SLOTS_*M_/4+255)/256,256>>>((float4*)memp,(const float4*)mem_in, B_*SLOTS_*M_/4);

    // weight splits (hi/lo bf16)
    {
        int n;
        n = L_*2*IT_*S_; split_kernel<<<(n/4+255)/256,256>>>(wt_gu, wtguh, wtgul, n);
        n = L_*S_*IT_;   split_kernel<<<(n/4+255)/256,256>>>(wt_d,  wtdh,  wtdl,  n);
        n = L_*2*IM_*H_; split_kernel<<<(n/4+255)/256,256>>>(wm_gu, wmguh, wmgul, n);
        n = L_*H_*IM_;   split_kernel<<<(n/4+255)/256,256>>>(wm_d,  wmdh,  wmdl,  n);
        n = V_*H_;       split_kernel<<<(n/4+255)/256,256>>>(lm_head_w, lmhh, lmhl, n);
    }

    dim3 trBlk(32,8);
    dim3 trGrd(S_/32, H_/32, B_);

    for (int st=0; st<HALT_STEPS_; st++){
        pooled1_kernel<<<dim3(B_,4), 512>>>();
        pooled2_kernel<<<B_, 512>>>();
        planner_kernel<<<B_, 256>>>(w1,b1,w2,b2,hdw,hdb,filmw,filmb,haltw,haltb,
                                    qw,qb,kw,kb,vw,vb,gw,gb,ow,ob,
                                    out + HALT_OFF + st*B_);
        z_update_kernel<<<B_*S_*H_/256, 256>>>(inputs, embed_w);

        for (int i=0; i<L_; i++){
            // ---- token mixer over S ----
            transpose_zt_split<<<trGrd, trBlk>>>();
            {
                size_t go = (size_t)i*2*IT_*S_;
                mma_gemm<1><<<dim3(IT_/128, (B_*H_)/128), 256, SMEM_G1>>>(
                    th, tl,
                    wtguh+go, wtgul+go,
                    wtguh+go+(size_t)IT_*S_, wtgul+go+(size_t)IT_*S_,
                    nullptr, ah, al, S_, IT_);
            }
            {
                size_t dof = (size_t)i*S_*IT_;
                mma_gemm<2><<<dim3(S_/128, (B_*H_)/128), 256, SMEM_G>>>(
                    ah, al, wtdh+dof, wtdl+dof, nullptr, nullptr,
                    tp, nullptr, nullptr, IT_, S_);
            }
            rmsnorm_t_kernel<<<B_*H_, 256>>>();
            transpose_tz_film_split<<<trGrd, trBlk>>>();
            // ---- channel mixer over H ----
            {
                size_t go = (size_t)i*2*IM_*H_;
                mma_gemm<1><<<dim3(IM_/128, (B_*S_)/128), 256, SMEM_G1>>>(
                    zh, zl,
                    wmguh+go, wmgul+go,
                    wmguh+go+(size_t)IM_*H_, wmgul+go+(size_t)IM_*H_,
                    nullptr, ah, al, H_, IM_);
            }
            {
                size_t dof = (size_t)i*H_*IM_;
                mma_gemm<2><<<dim3(H_/128, (B_*S_)/128), 256, SMEM_G>>>(
                    ah, al, wmdh+dof, wmdl+dof, nullptr, nullptr,
                    zp, nullptr, nullptr, IM_, H_);
            }
            rmsnorm_z_split_kernel<<<B_*S_, 256>>>();
        }
        // logits for this step
        mma_gemm<0><<<dim3(V_/128, (B_*S_)/128), 256, SMEM_G>>>(
            zh, zl, lmhh, lmhl, nullptr, nullptr,
            out + (size_t)st*B_*S_*V_, nullptr, nullptr, H_, V_);
    }

    // final state outputs
    copy4_kernel<<<(B_*S_*H_/4+255)/256, 256>>>((float4*)(out + ZL_OFF), (const float4*)zp, B_*S_*H_/4);
    copy4_kernel<<<(B_*P_/4+255)/256,    256>>>((float4*)(out + HOUT_OFF),(const float4*)hp, B_*P_/4);
    copy4_kernel<<<(B_*SLOTS_*M_/4+255)/256,256>>>((float4*)(out + MEM_OFF),(const float4*)memp, B_*SLOTS_*M_/4);
}